// round 7
// baseline (speedup 1.0000x reference)
#include <cuda_runtime.h>
#include <cstdint>

// Problem constants
#define S_LEN   2048
#define B_DIM   8
#define INDIM   512
#define ODIM    256
#define NROWS   16384          // B*S
#define SEG     128            // s-positions per A chunk (16 segments)
#define SUBSEG  64             // oscillator reseed granularity inside a segment

// Static device scratch (allocation APIs are forbidden; __device__ globals are
// the sanctioned workaround). Total 64 MB.
__device__ float g_C[16384 * 512];        // 32 MB: [:,0:256]=proj (LN'ed in place), [:,256:512]=residual
__device__ float g_A[SEG * 256 * 256];    // 32 MB: chunk of A_T[s][j][i] = A[s0+s,i,j]

// ---------------------------------------------------------------------------
// K1: C[m, n] = sum_k X[m,k] * W[n,k], W = rows of M (n<256) then W_res.
// 128x128x8 register-blocked SGEMM, 8x8 microtile, 256 threads.
// ---------------------------------------------------------------------------
__global__ __launch_bounds__(256) void k_proj(const float* __restrict__ X,
                                              const float* __restrict__ Mw,
                                              const float* __restrict__ Wr) {
    __shared__ float As[8][128];
    __shared__ float Bs[8][128];
    const int tid  = threadIdx.x;
    const int m0   = blockIdx.x * 128;
    const int n0   = blockIdx.y * 128;
    const int lrow = tid >> 1;           // 0..127
    const int lcol = (tid & 1) * 4;      // 0 or 4
    const int tx   = tid & 15;
    const int ty   = tid >> 4;

    const float* xrow = X + (size_t)(m0 + lrow) * 512;
    const float* wrow;
    {
        const int n = n0 + lrow;
        wrow = (n < 256) ? (Mw + (size_t)n * 512) : (Wr + (size_t)(n - 256) * 512);
    }

    float acc[8][8];
#pragma unroll
    for (int i = 0; i < 8; i++)
#pragma unroll
        for (int j = 0; j < 8; j++) acc[i][j] = 0.f;

    for (int k0 = 0; k0 < 512; k0 += 8) {
        const float4 av = *(const float4*)(xrow + k0 + lcol);
        const float4 bv = *(const float4*)(wrow + k0 + lcol);
        As[lcol + 0][lrow] = av.x; As[lcol + 1][lrow] = av.y;
        As[lcol + 2][lrow] = av.z; As[lcol + 3][lrow] = av.w;
        Bs[lcol + 0][lrow] = bv.x; Bs[lcol + 1][lrow] = bv.y;
        Bs[lcol + 2][lrow] = bv.z; Bs[lcol + 3][lrow] = bv.w;
        __syncthreads();
#pragma unroll
        for (int k = 0; k < 8; k++) {
            float a[8], b[8];
#pragma unroll
            for (int i = 0; i < 8; i++) a[i] = As[k][ty * 8 + i];
#pragma unroll
            for (int j = 0; j < 8; j++) b[j] = Bs[k][tx * 8 + j];
#pragma unroll
            for (int i = 0; i < 8; i++)
#pragma unroll
                for (int j = 0; j < 8; j++)
                    acc[i][j] = fmaf(a[i], b[j], acc[i][j]);
        }
        __syncthreads();
    }

#pragma unroll
    for (int i = 0; i < 8; i++) {
        float* crow = g_C + (size_t)(m0 + ty * 8 + i) * 512 + n0 + tx * 8;
        *(float4*)(crow)     = make_float4(acc[i][0], acc[i][1], acc[i][2], acc[i][3]);
        *(float4*)(crow + 4) = make_float4(acc[i][4], acc[i][5], acc[i][6], acc[i][7]);
    }
}

// ---------------------------------------------------------------------------
// K2: LayerNorm over 256 of C[:, 0:256], IN PLACE. Warp per row, 8 rows/block.
// Each thread loads its 8 values into registers before any write, so the
// in-place update is race-free within the warp.
// ---------------------------------------------------------------------------
__global__ void k_ln(const float* __restrict__ sc, const float* __restrict__ bi) {
    const int row  = blockIdx.x * 8 + threadIdx.y;
    const int lane = threadIdx.x;
    float* h = g_C + (size_t)row * 512;
    float v[8];
    float s = 0.f;
#pragma unroll
    for (int k = 0; k < 8; k++) { v[k] = h[lane + 32 * k]; s += v[k]; }
#pragma unroll
    for (int o = 16; o > 0; o >>= 1) s += __shfl_xor_sync(0xffffffffu, s, o);
    const float mu = s * (1.f / 256.f);
    float q = 0.f;
#pragma unroll
    for (int k = 0; k < 8; k++) { const float d = v[k] - mu; q = fmaf(d, d, q); }
#pragma unroll
    for (int o = 16; o > 0; o >>= 1) q += __shfl_xor_sync(0xffffffffu, q, o);
    const float inv = rsqrtf(q * (1.f / 256.f) + 1e-5f);
#pragma unroll
    for (int k = 0; k < 8; k++) {
        const int c = lane + 32 * k;
        h[c] = (v[k] - mu) * inv * sc[c] + bi[c];
    }
}

// ---------------------------------------------------------------------------
// K3: for s in [segBase, segBase+SEG), fill the chunk
//   g_A[(s-segBase)][j][i] = A[s,i,j] = sum_g P[i,j,g]*cos(2*pi*pos_s/T_ijg)
// via the numerically stable "magic circle" oscillator:
//   x <- x + eps*y ; y <- y - eps*x   with eps = 2*sin(pi/T)
// which satisfies exactly y_n = cos(n*theta), x_n = sin((n-1/2)*theta).
// Seeded by exact integer phase reduction (T is an exact integer) + cospif/sinpif.
// Thread = (i = threadIdx, j = blockIdx.x), 8 oscillators (g) in registers.
// blockIdx.y = subsegment (re-seeded) for wave balance + error control.
// ---------------------------------------------------------------------------
__global__ __launch_bounds__(256) void k_genA(const float* __restrict__ P,
                                              const float* __restrict__ per,
                                              const int*   __restrict__ pos,
                                              int segBase) {
    const int i    = threadIdx.x;
    const int j    = blockIdx.x;
    const int sub  = blockIdx.y;               // 0..1
    const int s0   = segBase + sub * SUBSEG;   // global s of first step
    const int base = (i * 256 + j) * 8;
    const int p0   = pos[s0];

    float pw[8], ep[8], xo[8], yo[8];
#pragma unroll
    for (int g = 0; g < 8; g++) {
        pw[g] = P[base + g];
        const int   Ti = (int)(per[base + g] + 0.5f);   // periods are exact integers
        const float Tf = (float)Ti;
        ep[g] = 2.f * sinpif(1.f / Tf);
        const int r = p0 % Ti;                           // exact phase reduction
        yo[g] = cospif((float)(2 * r) / Tf);             // cos(p0 * theta)
        xo[g] = sinpif((float)(2 * r - 1) / Tf);         // sin((p0 - 1/2) * theta)
    }

    float* outp = g_A + (size_t)(sub * SUBSEG) * 65536 + j * 256 + i;
#pragma unroll 2
    for (int s = 0; s < SUBSEG; s++) {
        float a = 0.f;
#pragma unroll
        for (int g = 0; g < 8; g++) a = fmaf(pw[g], yo[g], a);
        *outp = a;
        outp += 65536;
#pragma unroll
        for (int g = 0; g < 8; g++) {
            xo[g] = fmaf(ep[g], yo[g], xo[g]);     // uses old y
            yo[g] = fmaf(-ep[g], xo[g], yo[g]);    // uses NEW x
        }
    }
}

// ---------------------------------------------------------------------------
// K4: out[b,s,i] = sum_j t[b,s,j] * A[s,i,j] + residual[b,s,i]
// for s in the current segment. Block per s, thread per i. t tile staged in
// smem (broadcast reads), A streamed coalesced (i fastest) from the L2-resident
// chunk. t and residual come from the same g_C row (good locality).
// ---------------------------------------------------------------------------
__global__ __launch_bounds__(256) void k_contract(float* __restrict__ out,
                                                  int segBase) {
    __shared__ float tsh[8][256];
    const int sl = blockIdx.x;          // s within segment
    const int s  = segBase + sl;        // global s
    const int i  = threadIdx.x;
#pragma unroll
    for (int b = 0; b < 8; b++)
        tsh[b][i] = g_C[((size_t)b * S_LEN + s) * 512 + i];
    __syncthreads();

    float acc[8] = {0.f, 0.f, 0.f, 0.f, 0.f, 0.f, 0.f, 0.f};
    const float* Ab = g_A + (size_t)sl * 65536 + i;

#pragma unroll 2
    for (int j = 0; j < 256; j += 4) {
        float tb[8][4];
#pragma unroll
        for (int b = 0; b < 8; b++) {
            const float4 t4 = *(const float4*)&tsh[b][j];
            tb[b][0] = t4.x; tb[b][1] = t4.y; tb[b][2] = t4.z; tb[b][3] = t4.w;
        }
#pragma unroll
        for (int jj = 0; jj < 4; jj++) {
            const float a = Ab[(size_t)(j + jj) * 256];
#pragma unroll
            for (int b = 0; b < 8; b++) acc[b] = fmaf(a, tb[b][jj], acc[b]);
        }
    }

#pragma unroll
    for (int b = 0; b < 8; b++) {
        const float r = g_C[((size_t)b * S_LEN + s) * 512 + 256 + i];
        out[((size_t)b * S_LEN + s) * 256 + i] = acc[b] + r;
    }
}

// ---------------------------------------------------------------------------
// Inputs (metadata order): x, M, P, W_res, ln_scale, ln_bias, periods, positions
// ---------------------------------------------------------------------------
extern "C" void kernel_launch(void* const* d_in, const int* in_sizes, int n_in,
                              void* d_out, int out_size) {
    const float* x   = (const float*)d_in[0];
    const float* M   = (const float*)d_in[1];
    const float* P   = (const float*)d_in[2];
    const float* Wr  = (const float*)d_in[3];
    const float* lns = (const float*)d_in[4];
    const float* lnb = (const float*)d_in[5];
    const float* per = (const float*)d_in[6];
    const int*   pos = (const int*)d_in[7];
    float* out = (float*)d_out;
    (void)in_sizes; (void)n_in; (void)out_size;

    k_proj<<<dim3(128, 4), 256>>>(x, M, Wr);
    k_ln<<<2048, dim3(32, 8)>>>(lns, lnb);

    for (int seg = 0; seg < S_LEN / SEG; seg++) {
        const int segBase = seg * SEG;
        k_genA<<<dim3(256, SEG / SUBSEG), 256>>>(P, per, pos, segBase);
        k_contract<<<SEG, 256>>>(out, segBase);
    }
}

// round 8
// speedup vs baseline: 1.2765x; 1.2765x over previous
#include <cuda_runtime.h>
#include <cstdint>

// Problem constants
#define S_LEN   2048
#define B_DIM   8
#define INDIM   512
#define ODIM    256
#define NROWS   16384          // B*S
#define SEG     256            // s-positions per A chunk (8 segments)
#define SUBSEG  64             // oscillator reseed granularity inside a segment

// Static device scratch (allocation APIs are forbidden; __device__ globals are
// the sanctioned workaround). Total 96 MB.
__device__ float g_C[16384 * 512];        // 32 MB: [:,0:256]=proj (LN'ed in place), [:,256:512]=residual
__device__ float g_A[SEG * 256 * 256];    // 64 MB: chunk of A_T[s][j][i] = A[s0+s,i,j]

// ---------------------------------------------------------------------------
// K1: C[m, n] = sum_k X[m,k] * W[n,k], W = rows of M (n<256) then W_res.
// 128x128x8 register-blocked SGEMM, 8x8 microtile, 256 threads.
// ---------------------------------------------------------------------------
__global__ __launch_bounds__(256) void k_proj(const float* __restrict__ X,
                                              const float* __restrict__ Mw,
                                              const float* __restrict__ Wr) {
    __shared__ float As[8][128];
    __shared__ float Bs[8][128];
    const int tid  = threadIdx.x;
    const int m0   = blockIdx.x * 128;
    const int n0   = blockIdx.y * 128;
    const int lrow = tid >> 1;           // 0..127
    const int lcol = (tid & 1) * 4;      // 0 or 4
    const int tx   = tid & 15;
    const int ty   = tid >> 4;

    const float* xrow = X + (size_t)(m0 + lrow) * 512;
    const float* wrow;
    {
        const int n = n0 + lrow;
        wrow = (n < 256) ? (Mw + (size_t)n * 512) : (Wr + (size_t)(n - 256) * 512);
    }

    float acc[8][8];
#pragma unroll
    for (int i = 0; i < 8; i++)
#pragma unroll
        for (int j = 0; j < 8; j++) acc[i][j] = 0.f;

    for (int k0 = 0; k0 < 512; k0 += 8) {
        const float4 av = *(const float4*)(xrow + k0 + lcol);
        const float4 bv = *(const float4*)(wrow + k0 + lcol);
        As[lcol + 0][lrow] = av.x; As[lcol + 1][lrow] = av.y;
        As[lcol + 2][lrow] = av.z; As[lcol + 3][lrow] = av.w;
        Bs[lcol + 0][lrow] = bv.x; Bs[lcol + 1][lrow] = bv.y;
        Bs[lcol + 2][lrow] = bv.z; Bs[lcol + 3][lrow] = bv.w;
        __syncthreads();
#pragma unroll
        for (int k = 0; k < 8; k++) {
            float a[8], b[8];
#pragma unroll
            for (int i = 0; i < 8; i++) a[i] = As[k][ty * 8 + i];
#pragma unroll
            for (int j = 0; j < 8; j++) b[j] = Bs[k][tx * 8 + j];
#pragma unroll
            for (int i = 0; i < 8; i++)
#pragma unroll
                for (int j = 0; j < 8; j++)
                    acc[i][j] = fmaf(a[i], b[j], acc[i][j]);
        }
        __syncthreads();
    }

#pragma unroll
    for (int i = 0; i < 8; i++) {
        float* crow = g_C + (size_t)(m0 + ty * 8 + i) * 512 + n0 + tx * 8;
        *(float4*)(crow)     = make_float4(acc[i][0], acc[i][1], acc[i][2], acc[i][3]);
        *(float4*)(crow + 4) = make_float4(acc[i][4], acc[i][5], acc[i][6], acc[i][7]);
    }
}

// ---------------------------------------------------------------------------
// K2: LayerNorm over 256 of C[:, 0:256], IN PLACE. Warp per row, 8 rows/block.
// ---------------------------------------------------------------------------
__global__ void k_ln(const float* __restrict__ sc, const float* __restrict__ bi) {
    const int row  = blockIdx.x * 8 + threadIdx.y;
    const int lane = threadIdx.x;
    float* h = g_C + (size_t)row * 512;
    float v[8];
    float s = 0.f;
#pragma unroll
    for (int k = 0; k < 8; k++) { v[k] = h[lane + 32 * k]; s += v[k]; }
#pragma unroll
    for (int o = 16; o > 0; o >>= 1) s += __shfl_xor_sync(0xffffffffu, s, o);
    const float mu = s * (1.f / 256.f);
    float q = 0.f;
#pragma unroll
    for (int k = 0; k < 8; k++) { const float d = v[k] - mu; q = fmaf(d, d, q); }
#pragma unroll
    for (int o = 16; o > 0; o >>= 1) q += __shfl_xor_sync(0xffffffffu, q, o);
    const float inv = rsqrtf(q * (1.f / 256.f) + 1e-5f);
#pragma unroll
    for (int k = 0; k < 8; k++) {
        const int c = lane + 32 * k;
        h[c] = (v[k] - mu) * inv * sc[c] + bi[c];
    }
}

// ---------------------------------------------------------------------------
// K3: for s in [segBase, segBase+SEG), fill the chunk
//   g_A[(s-segBase)][j][i] = A[s,i,j] = sum_g P[i,j,g]*cos(2*pi*pos_s/T_ijg)
// via the numerically stable "magic circle" oscillator:
//   x <- x + eps*y ; y <- y - eps*x   with eps = 2*sin(pi/T)
// (exactly y_n = cos(n*theta), x_n = sin((n-1/2)*theta)). Seeded by exact
// integer phase reduction (T is an exact integer) + cospif/sinpif.
// Thread = (i = threadIdx, j = blockIdx.x), 8 oscillators (g) in registers.
// blockIdx.y = subsegment (re-seeded) for wave balance + error control.
// ---------------------------------------------------------------------------
__global__ __launch_bounds__(256) void k_genA(const float* __restrict__ P,
                                              const float* __restrict__ per,
                                              const int*   __restrict__ pos,
                                              int segBase) {
    const int i    = threadIdx.x;
    const int j    = blockIdx.x;
    const int sub  = blockIdx.y;               // 0..3
    const int s0   = segBase + sub * SUBSEG;   // global s of first step
    const int base = (i * 256 + j) * 8;
    const int p0   = pos[s0];

    float pw[8], ep[8], xo[8], yo[8];
#pragma unroll
    for (int g = 0; g < 8; g++) {
        pw[g] = P[base + g];
        const int   Ti = (int)(per[base + g] + 0.5f);   // periods are exact integers
        const float Tf = (float)Ti;
        ep[g] = 2.f * sinpif(1.f / Tf);
        const int r = p0 % Ti;                           // exact phase reduction
        yo[g] = cospif((float)(2 * r) / Tf);             // cos(p0 * theta)
        xo[g] = sinpif((float)(2 * r - 1) / Tf);         // sin((p0 - 1/2) * theta)
    }

    float* outp = g_A + (size_t)(sub * SUBSEG) * 65536 + j * 256 + i;
#pragma unroll 2
    for (int s = 0; s < SUBSEG; s++) {
        float a = 0.f;
#pragma unroll
        for (int g = 0; g < 8; g++) a = fmaf(pw[g], yo[g], a);
        *outp = a;
        outp += 65536;
#pragma unroll
        for (int g = 0; g < 8; g++) {
            xo[g] = fmaf(ep[g], yo[g], xo[g]);     // uses old y
            yo[g] = fmaf(-ep[g], xo[g], yo[g]);    // uses NEW x
        }
    }
}

// ---------------------------------------------------------------------------
// K4: out[b,s,i] = sum_j t[b,s,j] * A[s,i,j] + residual[b,s,i]
// for s in the current segment. Block per s with 1024 threads:
// thread = (jq, i), jq = j-quarter. Each thread reduces 64 j's (coalesced,
// unrolled A loads for MLP) into 8 batch accumulators; a conflict-free smem
// tree combines the 4 quarters. 4x the resident threads vs R6's version.
// ---------------------------------------------------------------------------
__global__ __launch_bounds__(1024) void k_contract(float* __restrict__ out,
                                                   int segBase) {
    __shared__ float tsh[8][256];
    __shared__ float red[3][8][256];    // partials from jq = 1..3
    const int sl  = blockIdx.x;         // s within segment
    const int s   = segBase + sl;       // global s
    const int tid = threadIdx.x;
    const int i   = tid & 255;
    const int jq  = tid >> 8;           // 0..3

    // stage t[b,s,:] (1024 threads load 2048 values)
#pragma unroll
    for (int v = tid; v < 2048; v += 1024) {
        const int b = v >> 8, c = v & 255;
        tsh[b][c] = g_C[((size_t)b * S_LEN + s) * 512 + c];
    }
    __syncthreads();

    float acc[8] = {0.f, 0.f, 0.f, 0.f, 0.f, 0.f, 0.f, 0.f};
    const float* Ab = g_A + (size_t)sl * 65536 + i;
    const int j0 = jq * 64;

#pragma unroll 2
    for (int j = j0; j < j0 + 64; j += 8) {
        float av[8];
#pragma unroll
        for (int jj = 0; jj < 8; jj++)
            av[jj] = Ab[(size_t)(j + jj) * 256];
#pragma unroll
        for (int jj = 0; jj < 8; jj++) {
            const float a = av[jj];
#pragma unroll
            for (int b = 0; b < 8; b++)
                acc[b] = fmaf(a, tsh[b][j + jj], acc[b]);
        }
    }

    if (jq > 0) {
#pragma unroll
        for (int b = 0; b < 8; b++) red[jq - 1][b][i] = acc[b];
    }
    __syncthreads();

    if (jq == 0) {
#pragma unroll
        for (int b = 0; b < 8; b++) {
            const float t = acc[b] + red[0][b][i] + red[1][b][i] + red[2][b][i];
            const float r = g_C[((size_t)b * S_LEN + s) * 512 + 256 + i];
            out[((size_t)b * S_LEN + s) * 256 + i] = t + r;
        }
    }
}

// ---------------------------------------------------------------------------
// Inputs (metadata order): x, M, P, W_res, ln_scale, ln_bias, periods, positions
// ---------------------------------------------------------------------------
extern "C" void kernel_launch(void* const* d_in, const int* in_sizes, int n_in,
                              void* d_out, int out_size) {
    const float* x   = (const float*)d_in[0];
    const float* M   = (const float*)d_in[1];
    const float* P   = (const float*)d_in[2];
    const float* Wr  = (const float*)d_in[3];
    const float* lns = (const float*)d_in[4];
    const float* lnb = (const float*)d_in[5];
    const float* per = (const float*)d_in[6];
    const int*   pos = (const int*)d_in[7];
    float* out = (float*)d_out;
    (void)in_sizes; (void)n_in; (void)out_size;

    k_proj<<<dim3(128, 4), 256>>>(x, M, Wr);
    k_ln<<<2048, dim3(32, 8)>>>(lns, lnb);

    for (int seg = 0; seg < S_LEN / SEG; seg++) {
        const int segBase = seg * SEG;
        k_genA<<<dim3(256, SEG / SUBSEG), 256>>>(P, per, pos, segBase);
        k_contract<<<SEG, 1024>>>(out, segBase);
    }
}

// round 9
// speedup vs baseline: 1.5810x; 1.2385x over previous
#include <cuda_runtime.h>
#include <cuda_fp16.h>
#include <cstdint>

// Problem constants
#define S_LEN   2048
#define B_DIM   8
#define INDIM   512
#define ODIM    256
#define NROWS   16384          // B*S
#define SEG     512            // s-positions per A chunk (4 segments)
#define SUBSEG  128            // oscillator reseed granularity

typedef unsigned long long u64;

// ---- packed fp32x2 helpers (Blackwell f32x2 pipe) -------------------------
__device__ __forceinline__ u64 pack2(float lo, float hi) {
    u64 r; asm("mov.b64 %0, {%1, %2};" : "=l"(r) : "f"(lo), "f"(hi)); return r;
}
__device__ __forceinline__ float2 unpack2(u64 v) {
    float2 f; asm("mov.b64 {%0, %1}, %2;" : "=f"(f.x), "=f"(f.y) : "l"(v)); return f;
}
__device__ __forceinline__ u64 fma2(u64 a, u64 b, u64 c) {
    u64 d; asm("fma.rn.f32x2 %0, %1, %2, %3;" : "=l"(d) : "l"(a), "l"(b), "l"(c)); return d;
}
__device__ __forceinline__ u64 add2(u64 a, u64 b) {
    u64 d; asm("add.rn.f32x2 %0, %1, %2;" : "=l"(d) : "l"(a), "l"(b)); return d;
}

// Static device scratch (allocation APIs are forbidden). Total 96 MB.
__device__ float  g_C[16384 * 512];            // 32 MB: [:,0:256]=proj (LN in place), [:,256:512]=residual
__device__ __half g_A[(size_t)SEG * 65536];    // 64 MB: chunk A_T[s][j][i] = A[s0+s,i,j], fp16

// ---------------------------------------------------------------------------
// K1: C[m,n] = sum_k X[m,k]*W[n,k]; W = rows of M (n<256) then W_res.
// 128x128x8 SGEMM, 8x8 microtile, packed f32x2 inner product (j packed).
// ---------------------------------------------------------------------------
__global__ __launch_bounds__(256) void k_proj(const float* __restrict__ X,
                                              const float* __restrict__ Mw,
                                              const float* __restrict__ Wr) {
    __shared__ float As[8][128];
    __shared__ float Bs[8][128];
    const int tid  = threadIdx.x;
    const int m0   = blockIdx.x * 128;
    const int n0   = blockIdx.y * 128;
    const int lrow = tid >> 1;
    const int lcol = (tid & 1) * 4;
    const int tx   = tid & 15;
    const int ty   = tid >> 4;

    const float* xrow = X + (size_t)(m0 + lrow) * 512;
    const float* wrow;
    {
        const int n = n0 + lrow;
        wrow = (n < 256) ? (Mw + (size_t)n * 512) : (Wr + (size_t)(n - 256) * 512);
    }

    u64 acc[8][4];
#pragma unroll
    for (int i = 0; i < 8; i++)
#pragma unroll
        for (int jp = 0; jp < 4; jp++) acc[i][jp] = 0ull;

    for (int k0 = 0; k0 < 512; k0 += 8) {
        const float4 av = *(const float4*)(xrow + k0 + lcol);
        const float4 bv = *(const float4*)(wrow + k0 + lcol);
        As[lcol + 0][lrow] = av.x; As[lcol + 1][lrow] = av.y;
        As[lcol + 2][lrow] = av.z; As[lcol + 3][lrow] = av.w;
        Bs[lcol + 0][lrow] = bv.x; Bs[lcol + 1][lrow] = bv.y;
        Bs[lcol + 2][lrow] = bv.z; Bs[lcol + 3][lrow] = bv.w;
        __syncthreads();
#pragma unroll
        for (int k = 0; k < 8; k++) {
            u64 ap[8], bp[4];
            const u64* bs2 = (const u64*)&Bs[k][tx * 8];   // 4 packed j-pairs
#pragma unroll
            for (int jp = 0; jp < 4; jp++) bp[jp] = bs2[jp];
#pragma unroll
            for (int i = 0; i < 8; i++) {
                const float a = As[k][ty * 8 + i];
                ap[i] = pack2(a, a);
            }
#pragma unroll
            for (int i = 0; i < 8; i++)
#pragma unroll
                for (int jp = 0; jp < 4; jp++)
                    acc[i][jp] = fma2(ap[i], bp[jp], acc[i][jp]);
        }
        __syncthreads();
    }

#pragma unroll
    for (int i = 0; i < 8; i++) {
        u64* crow = (u64*)(g_C + (size_t)(m0 + ty * 8 + i) * 512 + n0 + tx * 8);
#pragma unroll
        for (int jp = 0; jp < 4; jp++) crow[jp] = acc[i][jp];
    }
}

// ---------------------------------------------------------------------------
// K2: LayerNorm over 256 of C[:,0:256], IN PLACE. Warp per row, 8 rows/block.
// ---------------------------------------------------------------------------
__global__ void k_ln(const float* __restrict__ sc, const float* __restrict__ bi) {
    const int row  = blockIdx.x * 8 + threadIdx.y;
    const int lane = threadIdx.x;
    float* h = g_C + (size_t)row * 512;
    float v[8];
    float s = 0.f;
#pragma unroll
    for (int k = 0; k < 8; k++) { v[k] = h[lane + 32 * k]; s += v[k]; }
#pragma unroll
    for (int o = 16; o > 0; o >>= 1) s += __shfl_xor_sync(0xffffffffu, s, o);
    const float mu = s * (1.f / 256.f);
    float q = 0.f;
#pragma unroll
    for (int k = 0; k < 8; k++) { const float d = v[k] - mu; q = fmaf(d, d, q); }
#pragma unroll
    for (int o = 16; o > 0; o >>= 1) q += __shfl_xor_sync(0xffffffffu, q, o);
    const float inv = rsqrtf(q * (1.f / 256.f) + 1e-5f);
#pragma unroll
    for (int k = 0; k < 8; k++) {
        const int c = lane + 32 * k;
        h[c] = (v[k] - mu) * inv * sc[c] + bi[c];
    }
}

// ---------------------------------------------------------------------------
// K3: fill g_A[(s-segBase)][j][i] = A[s,i,j] = sum_g P[i,j,g]*cos(2*pi*pos_s/T)
// via the exact "magic circle" oscillator (x<-x+eps*y; y<-y-eps*x,
// eps=2*sin(pi/T) => y_n = cos(n*theta) exactly), stepped with packed f32x2
// (g-pairs). Seeded by exact integer phase reduction + cospif/sinpif.
// Thread=(i,j-block), blockIdx.y = 128-step subsegment.
// ---------------------------------------------------------------------------
__global__ __launch_bounds__(256) void k_genA(const float* __restrict__ P,
                                              const float* __restrict__ per,
                                              const int*   __restrict__ pos,
                                              int segBase) {
    const int i    = threadIdx.x;
    const int j    = blockIdx.x;
    const int sub  = blockIdx.y;               // 0..3
    const int s0   = segBase + sub * SUBSEG;
    const int base = (i * 256 + j) * 8;
    const int p0   = pos[s0];

    float pw[8], ep[8], xo[8], yo[8];
#pragma unroll
    for (int g = 0; g < 8; g++) {
        pw[g] = P[base + g];
        const int   Ti = (int)(per[base + g] + 0.5f);   // periods are exact integers
        const float Tf = (float)Ti;
        ep[g] = 2.f * sinpif(1.f / Tf);
        const int r = p0 % Ti;                           // exact phase reduction
        yo[g] = cospif((float)(2 * r) / Tf);             // cos(p0*theta)
        xo[g] = sinpif((float)(2 * r - 1) / Tf);         // sin((p0-1/2)*theta)
    }

    u64 pw2[4], ep2[4], nep2[4], x2[4], y2[4];
#pragma unroll
    for (int k = 0; k < 4; k++) {
        pw2[k]  = pack2(pw[2 * k], pw[2 * k + 1]);
        ep2[k]  = pack2(ep[2 * k], ep[2 * k + 1]);
        nep2[k] = pack2(-ep[2 * k], -ep[2 * k + 1]);
        x2[k]   = pack2(xo[2 * k], xo[2 * k + 1]);
        y2[k]   = pack2(yo[2 * k], yo[2 * k + 1]);
    }

    __half* outp = g_A + (size_t)(sub * SUBSEG) * 65536 + j * 256 + i;
#pragma unroll 2
    for (int s = 0; s < SUBSEG; s++) {
        u64 d0 = fma2(pw2[0], y2[0], 0ull);
        u64 d1 = fma2(pw2[1], y2[1], 0ull);
        d0 = fma2(pw2[2], y2[2], d0);
        d1 = fma2(pw2[3], y2[3], d1);
        const float2 f = unpack2(add2(d0, d1));
        *outp = __float2half_rn(f.x + f.y);
        outp += 65536;
#pragma unroll
        for (int k = 0; k < 4; k++) x2[k] = fma2(ep2[k], y2[k], x2[k]);   // old y
#pragma unroll
        for (int k = 0; k < 4; k++) y2[k] = fma2(nep2[k], x2[k], y2[k]);  // new x
    }
}

// ---------------------------------------------------------------------------
// K4: out[b,s,i] = sum_j t[b,s,j]*A[s,i,j] + residual[b,s,i].
// Block per s (512 threads): thread=(jq 0..3, ip 0..127) handles 2 i's (half2
// A loads, 128B/warp) x 64 j's x all 8 b (packed f32x2 accumulators against
// duplicated-t pairs staged in smem). 2-stage smem tree over j-quarters.
// ---------------------------------------------------------------------------
__global__ __launch_bounds__(512) void k_contract(float* __restrict__ out,
                                                  int segBase) {
    __shared__ u64 t2[8][256];          // (t,t) duplicated pairs
    __shared__ u64 red[3][8][128];      // packed i-pair partials, jq=1..3
    const int sl  = blockIdx.x;
    const int s   = segBase + sl;
    const int tid = threadIdx.x;
    const int ip  = tid & 127;          // i-pair
    const int jq  = tid >> 7;           // 0..3

    for (int v = tid; v < 2048; v += 512) {
        const int b = v >> 8, c = v & 255;
        const float t = g_C[((size_t)b * S_LEN + s) * 512 + c];
        t2[b][c] = pack2(t, t);
    }
    __syncthreads();

    u64 acc[8] = {0ull, 0ull, 0ull, 0ull, 0ull, 0ull, 0ull, 0ull};
    const __half2* Ab = ((const __half2*)g_A) + (size_t)sl * 32768 + ip;
    const int j0 = jq * 64;

#pragma unroll 2
    for (int j = j0; j < j0 + 64; j += 8) {
        __half2 av[8];
#pragma unroll
        for (int jj = 0; jj < 8; jj++)
            av[jj] = Ab[(size_t)(j + jj) * 128];
#pragma unroll
        for (int jj = 0; jj < 8; jj++) {
            const float2 af = __half22float2(av[jj]);
            const u64 a2 = pack2(af.x, af.y);
#pragma unroll
            for (int b = 0; b < 8; b++)
                acc[b] = fma2(t2[b][j + jj], a2, acc[b]);
        }
    }

    if (jq > 0) {
#pragma unroll
        for (int b = 0; b < 8; b++) red[jq - 1][b][ip] = acc[b];
    }
    __syncthreads();

    if (jq == 0) {
#pragma unroll
        for (int b = 0; b < 8; b++) {
            const u64 t = add2(add2(acc[b], red[0][b][ip]),
                               add2(red[1][b][ip], red[2][b][ip]));
            const float2 sf = unpack2(t);
            const float2 r  = *(const float2*)&g_C[((size_t)b * S_LEN + s) * 512 + 256 + 2 * ip];
            float2 o; o.x = sf.x + r.x; o.y = sf.y + r.y;
            *(float2*)&out[((size_t)b * S_LEN + s) * 256 + 2 * ip] = o;
        }
    }
}

// ---------------------------------------------------------------------------
// Inputs (metadata order): x, M, P, W_res, ln_scale, ln_bias, periods, positions
// ---------------------------------------------------------------------------
extern "C" void kernel_launch(void* const* d_in, const int* in_sizes, int n_in,
                              void* d_out, int out_size) {
    const float* x   = (const float*)d_in[0];
    const float* M   = (const float*)d_in[1];
    const float* P   = (const float*)d_in[2];
    const float* Wr  = (const float*)d_in[3];
    const float* lns = (const float*)d_in[4];
    const float* lnb = (const float*)d_in[5];
    const float* per = (const float*)d_in[6];
    const int*   pos = (const int*)d_in[7];
    float* out = (float*)d_out;
    (void)in_sizes; (void)n_in; (void)out_size;

    k_proj<<<dim3(128, 4), 256>>>(x, M, Wr);
    k_ln<<<2048, dim3(32, 8)>>>(lns, lnb);

    for (int seg = 0; seg < S_LEN / SEG; seg++) {
        const int segBase = seg * SEG;
        k_genA<<<dim3(256, SEG / SUBSEG), 256>>>(P, per, pos, segBase);
        k_contract<<<SEG, 512>>>(out, segBase);
    }
}